// round 8
// baseline (speedup 1.0000x reference)
#include <cuda_runtime.h>
#include <cuda_fp16.h>
#include <math.h>

#define HH 512
#define WW 512
#define NVIEW 768
#define NDCT 736
#define NT 725

#define PW 513
#define PH 514
#define CAP 5000          // smem window capacity (entries), 40KB
#define CHUNK 64

// fp16 pair table: g_ph[py*PW+px] = { half2(c0,c1)@x=px-1, half2(c0,c1)@x=px },
// image row y = py-1, zero border. 8 bytes/entry.
struct __align__(8) HPair { __half2 lo, hi; };
__device__ HPair g_ph[PH * PW];

__global__ void build_pair(const float* __restrict__ in) {
    int i = blockIdx.x * blockDim.x + threadIdx.x;
    if (i >= PH * PW) return;
    int py = i / PW;
    int px = i - py * PW;
    int y = py - 1;
    int x0 = px - 1;
    float l0 = 0.0f, l1 = 0.0f, h0 = 0.0f, h1 = 0.0f;
    if (y >= 0 && y < HH) {
        if (x0 >= 0) {
            l0 = in[y * WW + x0];
            l1 = in[HH * WW + y * WW + x0];
        }
        if (px < WW) {
            h0 = in[y * WW + px];
            h1 = in[HH * WW + y * WW + px];
        }
    }
    HPair p;
    p.lo = __floats2half2_rn(l0, l1);
    p.hi = __floats2half2_rn(h0, h1);
    g_ph[i] = p;
}

// Clip t so x(t)=bx-sn*t, y(t)=by+c*t stay inside (-0.999, 511.999).
__device__ __forceinline__ void clip_ray(float bx, float by, float sn, float c,
                                         int& k0, int& k1) {
    float tlo = -362.0f, thi = 362.0f;
    const float lo = -0.999f;
    const float hi = 511.999f;
    if (sn > 1e-7f) {
        float inv = __frcp_rn(sn);
        tlo = fmaxf(tlo, (bx - hi) * inv);
        thi = fminf(thi, (bx - lo) * inv);
    } else if (bx <= lo || bx >= hi) {
        thi = tlo - 1.0f;
    }
    if (c > 1e-7f) {
        float inv = __frcp_rn(c);
        tlo = fmaxf(tlo, (lo - by) * inv);
        thi = fminf(thi, (hi - by) * inv);
    } else if (c < -1e-7f) {
        float inv = __frcp_rn(c);
        tlo = fmaxf(tlo, (hi - by) * inv);
        thi = fminf(thi, (lo - by) * inv);
    } else if (by <= lo || by >= hi) {
        thi = tlo - 1.0f;
    }
    k0 = max(0, (int)ceilf(tlo + 362.0f));
    k1 = min(NT - 1, (int)floorf(thi + 362.0f));
}

#define MAGIC 8388608.0f  // 2^23
#define DEAD_KB (1 << 30)

// Bilinear tap math given the two row entries (both channels packed).
#define SAMPLE_CORE(xp, yp, R0, R1, pacc)                              \
    do {                                                               \
        float _wx = (xp) - (_sx - MAGIC);                              \
        float _wy = (yp) - (_sy - MAGIC);                              \
        __half2 _wxh = __float2half2_rn(_wx);                          \
        __half2 _wyh = __float2half2_rn(_wy);                          \
        __half2 _a0 = __hfma2(_wxh, __hsub2((R0).hi, (R0).lo), (R0).lo); \
        __half2 _a1 = __hfma2(_wxh, __hsub2((R1).hi, (R1).lo), (R1).lo); \
        (pacc) = __hadd2((pacc), __hfma2(_wyh, __hsub2(_a1, _a0), _a0)); \
    } while (0)

// MODE 0: kernel A (|cos|>=sin). MODE 1: kernel B (sin>|cos|).
// DPB detectors per block, DPW per warp, TS t-stride (= 32/DPW).
template <int DPB, int DPW, int TS, int MODE>
__global__ void __launch_bounds__(256) radonK(float* __restrict__ out) {
    __shared__ HPair win[CAP];
    __shared__ int sK0, sK1;

    int lane = threadIdx.x & 31;
    int warp = threadIdx.x >> 5;
    int si = lane & (DPW - 1);
    int ti = lane / DPW;                 // 0..TS-1
    int sbase = blockIdx.x * DPB;
    int s = sbase + (warp & 1) * DPW + si;

    int vbase, vmax;
    if (MODE == 0) {
        int g = blockIdx.y;
        if (g < 49) { vbase = g * 4;             vmax = 192; }
        else        { vbase = 576 + (g - 49) * 4; vmax = 767; }
    } else {
        vbase = 193 + blockIdx.y * 4;
        vmax = 575;
    }
    int vwant = vbase + (warp >> 1);
    bool alive = (vwant <= vmax);
    int v = alive ? vwant : vmax;

    if (threadIdx.x == 0) { sK0 = NT; sK1 = -1; }
    __syncthreads();

    const float DTH = (float)(M_PI / 768.0);
    float theta = (float)v * DTH;
    float sn, c;
    sincosf(theta, &sn, &c);
    float sf = (float)s - 367.5f;
    float bx = fmaf(sf, c, 255.5f);
    float by = fmaf(sf, sn, 255.5f);
    int k0, k1;
    clip_ray(bx, by, sn, c, k0, k1);
    float bxp = bx + 1.0f;
    float byp = by + 1.0f;

    bool live = alive && (k0 <= k1);
    if (live) {
        atomicMin(&sK0, k0);
        atomicMax(&sK1, k1);
    }
    __syncthreads();
    int K0 = sK0, K1 = sK1;
    if (K1 < K0) return;   // block-uniform: no ray intersects image

    // Corner-view trig for window bounds (contiguous theta within block).
    float thl = (float)vbase * DTH;
    float thh = (float)min(vbase + 3, vmax) * DTH;
    float snl, cl, snh, ch2;
    sincosf(thl, &snl, &cl);
    sincosf(thh, &snh, &ch2);
    float sAf = (float)sbase - 367.5f;
    float sBf = (float)(sbase + DPB - 1) - 367.5f;

    float accx = 0.0f, accy = 0.0f;

    for (int cb = K0; cb <= K1; cb += CHUNK) {
        float t0 = (float)cb - 362.0f;
        float t1 = t0 + (float)(CHUNK - 1);

        // 8 corners in padded coords (center 256.5)
        float xmn = 1e9f, xmx = -1e9f, ymn = 1e9f, ymx = -1e9f;
        auto upd = [&](float C, float S, float sv, float tv) {
            float x = fmaf(sv, C, fmaf(tv, -S, 256.5f));
            float y = fmaf(sv, S, fmaf(tv, C, 256.5f));
            xmn = fminf(xmn, x); xmx = fmaxf(xmx, x);
            ymn = fminf(ymn, y); ymx = fmaxf(ymx, y);
        };
        upd(cl, snl, sAf, t0); upd(cl, snl, sAf, t1);
        upd(cl, snl, sBf, t0); upd(cl, snl, sBf, t1);
        upd(ch2, snh, sAf, t0); upd(ch2, snh, sAf, t1);
        upd(ch2, snh, sBf, t0); upd(ch2, snh, sBf, t1);

        int ry0 = max(0, (int)floorf(ymn) - 1);
        int ry1 = min(PH - 1, (int)floorf(ymx) + 2);
        int rx0 = max(0, (int)floorf(xmn) - 1);
        int rx1 = min(PW - 1, (int)floorf(xmx) + 1);
        int Hh = ry1 - ry0 + 1;
        int Wd = rx1 - rx0 + 1;
        int WP = Wd | 1;                       // odd padded width (bank spread)
        bool useSmem = (Hh > 0) && (Wd > 0) && (Hh * WP <= CAP);

        __syncthreads();   // prior chunk's sampling done before overwrite
        if (useSmem) {
            for (int r = warp; r < Hh; r += 8) {
                const HPair* src = &g_ph[(ry0 + r) * PW + rx0];
                HPair* dst = &win[r * WP];
                for (int cc = lane; cc < Wd; cc += 32)
                    dst[cc] = src[cc];
            }
        }
        __syncthreads();

        int winoff = ry0 * WP + rx0;
        int kb = live ? (cb + ti - k0) : DEAD_KB;
        int span = live ? (k1 - k0) : 0;
        float tf = (float)(cb + ti) - 362.0f;

        __half2 pacc = __float2half2_rn(0.0f);
        if (useSmem) {
            #pragma unroll
            for (int u = 0; u < CHUNK / TS; ++u) {
                if ((unsigned)(kb + TS * u) <= (unsigned)span) {
                    float tfu = tf + (float)(TS * u);
                    float xp = fmaf(tfu, -sn, bxp);
                    float yp = fmaf(tfu, c, byp);
                    float _sx = __fadd_rd(xp, MAGIC);
                    float _sy = __fadd_rd(yp, MAGIC);
                    int ixp = __float_as_int(_sx) & 0x7FFFFF;
                    int iyp = __float_as_int(_sy) & 0x7FFFFF;
                    int base = iyp * WP + ixp - winoff;
                    HPair r0 = win[base];
                    HPair r1 = win[base + WP];
                    SAMPLE_CORE(xp, yp, r0, r1, pacc);
                }
            }
        } else {
            #pragma unroll
            for (int u = 0; u < CHUNK / TS; ++u) {
                if ((unsigned)(kb + TS * u) <= (unsigned)span) {
                    float tfu = tf + (float)(TS * u);
                    float xp = fmaf(tfu, -sn, bxp);
                    float yp = fmaf(tfu, c, byp);
                    float _sx = __fadd_rd(xp, MAGIC);
                    float _sy = __fadd_rd(yp, MAGIC);
                    int ixp = __float_as_int(_sx) & 0x7FFFFF;
                    int iyp = __float_as_int(_sy) & 0x7FFFFF;
                    int base = iyp * PW + ixp;
                    HPair r0 = g_ph[base];
                    HPair r1 = g_ph[base + PW];
                    SAMPLE_CORE(xp, yp, r0, r1, pacc);
                }
            }
        }
        float2 f = __half22float2(pacc);
        accx += f.x;
        accy += f.y;
    }

    // Reduce across t-groups (lanes differing above det bits).
    #pragma unroll
    for (int off = DPW; off < 32; off <<= 1) {
        accx += __shfl_xor_sync(0xFFFFFFFFu, accx, off);
        accy += __shfl_xor_sync(0xFFFFFFFFu, accy, off);
    }
    if (lane < DPW && alive) {
        out[v * NDCT + s] = accx;
        out[NVIEW * NDCT + v * NDCT + s] = accy;
    }
}

extern "C" void kernel_launch(void* const* d_in, const int* in_sizes, int n_in,
                              void* d_out, int out_size) {
    const float* in = (const float*)d_in[0];
    float* out = (float*)d_out;

    build_pair<<<(PH * PW + 255) / 256, 256>>>(in);

    // A: 16 det x 4 views per block; view groups: 49 (v 0..192) + 48 (v 576..767).
    dim3 gridA(NDCT / 16, 97);
    radonK<16, 8, 4, 0><<<gridA, 256>>>(out);

    // B: 8 det x 4 views per block; 96 groups covering v 193..575.
    dim3 gridB(NDCT / 8, 96);
    radonK<8, 4, 8, 1><<<gridB, 256>>>(out);
}